// round 4
// baseline (speedup 1.0000x reference)
#include <cuda_runtime.h>
#include <cuda_bf16.h>
#include <cstdint>

#define D_FEAT 32

// ---------------------------------------------------------------------------
// out[n,:] = x[n,:] * sum_{e: tgt[e]==n} W[e]
// (reference gathers AND scatters on target => [E,32] message matrix
// factorizes into a scalar segment-sum + broadcast multiply).
// Per-node scalar accumulator lives inside d_out at out[n*32]; the whole
// buffer is zeroed by a memset graph node (contiguous memset streams at
// near-HBM rate; the old scattered-slot zero kernel was latency-bound).
// ---------------------------------------------------------------------------

// Pass 1: scalar segment-sum of W onto target-node slots.
// Vectorized: each thread loads 4 edges as int4 + float4, issues 4 REDs.
__global__ void accum_kernel(const int4* __restrict__ tgt4,
                             const float4* __restrict__ W4,
                             float* __restrict__ out,
                             int n_quads, unsigned int N)
{
    int i = blockIdx.x * blockDim.x + threadIdx.x;
    if (i < n_quads) {
        int4   t4 = tgt4[i];
        float4 w4 = W4[i];
        unsigned int t;
        t = (unsigned int)t4.x; if (t < N) atomicAdd(&out[(size_t)t * D_FEAT], w4.x);
        t = (unsigned int)t4.y; if (t < N) atomicAdd(&out[(size_t)t * D_FEAT], w4.y);
        t = (unsigned int)t4.z; if (t < N) atomicAdd(&out[(size_t)t * D_FEAT], w4.z);
        t = (unsigned int)t4.w; if (t < N) atomicAdd(&out[(size_t)t * D_FEAT], w4.w);
    }
}

// Scalar tail (E % 4 != 0) — not hit for E=1.6M, kept for generality.
__global__ void accum_tail_kernel(const int* __restrict__ tgt,
                                  const float* __restrict__ W,
                                  float* __restrict__ out,
                                  int start, int E, unsigned int N)
{
    int e = start + blockIdx.x * blockDim.x + threadIdx.x;
    if (e < E) {
        unsigned int t = (unsigned int)tgt[e];
        if (t < N) atomicAdd(&out[(size_t)t * D_FEAT], W[e]);
    }
}

// Pass 2: out[n,:] = x[n,:] * s, s = out[n*32].
// 8 threads per node, one float4 each; all 8 lanes of a node sit in one
// warp (8 | 32, n_vec % 32 == 0), so __syncwarp() orders the scalar read
// before the lane covering slot 0 overwrites it.
__global__ void mul_kernel(const float4* __restrict__ x4,
                           float4* __restrict__ out4,
                           int n_vec)  // = N * 8
{
    int i = blockIdx.x * blockDim.x + threadIdx.x;
    if (i < n_vec) {
        int node = i >> 3;
        const float* out_s = (const float*)out4;
        float s = __ldg(&out_s[(size_t)node * D_FEAT]);
        float4 v = x4[i];
        __syncwarp();
        v.x *= s; v.y *= s; v.z *= s; v.w *= s;
        out4[i] = v;
    }
}

// Inputs (metadata order): edge_index int32 [2, E], x f32 [N, 32], W f32 [E].
// Output: f32 [N, 32].
extern "C" void kernel_launch(void* const* d_in, const int* in_sizes, int n_in,
                              void* d_out, int out_size)
{
    const int*   edge_index = (const int*)d_in[0];
    const float* x          = (const float*)d_in[1];
    const float* W          = (const float*)d_in[2];
    float*       out        = (float*)d_out;

    const int E = in_sizes[2];           // number of edges (= len(W))
    const int N = in_sizes[1] / D_FEAT;  // number of nodes

    const int* tgt = edge_index + (size_t)E;  // second row of [2, E]

    // Pass 0: zero the whole output buffer (memset node; contiguous stream).
    cudaMemsetAsync(out, 0, (size_t)out_size * sizeof(float), 0);

    // Pass 1: segment-sum W by target into out[n*32]
    {
        int n_quads = E / 4;
        int threads = 256;
        int blocks = (n_quads + threads - 1) / threads;
        if (blocks > 0)
            accum_kernel<<<blocks, threads>>>((const int4*)tgt, (const float4*)W,
                                              out, n_quads, (unsigned int)N);
        int tail_start = n_quads * 4;
        int tail = E - tail_start;
        if (tail > 0)
            accum_tail_kernel<<<1, 256>>>(tgt, W, out, tail_start, E,
                                          (unsigned int)N);
    }

    // Pass 2: broadcast multiply (overwrites all of out, including slots)
    {
        int n_vec = N * (D_FEAT / 4);    // N * 8 float4s
        int threads = 512;
        int blocks = (n_vec + threads - 1) / threads;
        mul_kernel<<<blocks, threads>>>((const float4*)x, (float4*)out, n_vec);
    }
}

// round 6
// speedup vs baseline: 1.0250x; 1.0250x over previous
#include <cuda_runtime.h>
#include <cuda_bf16.h>
#include <cstdint>

#define D_FEAT 32

// ---------------------------------------------------------------------------
// out[n,:] = x[n,:] * sum_{e: tgt[e]==n} W[e]
// (reference gathers AND scatters on target => the [E,32] message matrix
// factorizes into a scalar segment-sum + broadcast multiply).
// Per-node scalar accumulator lives inside d_out at out[n*32]; buffer is
// zeroed by a memset graph node.
// ---------------------------------------------------------------------------

// Pass 1: scalar segment-sum of W onto target-node slots.
// Each thread loads 4 edges (int4 + float4) and issues 4 REDs.
__global__ void accum_kernel(const int4* __restrict__ tgt4,
                             const float4* __restrict__ W4,
                             float* __restrict__ out,
                             int n_quads, unsigned int N)
{
    int i = blockIdx.x * blockDim.x + threadIdx.x;
    if (i < n_quads) {
        int4   t4 = tgt4[i];
        float4 w4 = W4[i];
        unsigned int t;
        t = (unsigned int)t4.x; if (t < N) atomicAdd(&out[(size_t)t * D_FEAT], w4.x);
        t = (unsigned int)t4.y; if (t < N) atomicAdd(&out[(size_t)t * D_FEAT], w4.y);
        t = (unsigned int)t4.z; if (t < N) atomicAdd(&out[(size_t)t * D_FEAT], w4.z);
        t = (unsigned int)t4.w; if (t < N) atomicAdd(&out[(size_t)t * D_FEAT], w4.w);
    }
}

// Scalar tail (E % 4 != 0) — not hit for E = 1.6M.
__global__ void accum_tail_kernel(const int* __restrict__ tgt,
                                  const float* __restrict__ W,
                                  float* __restrict__ out,
                                  int start, int E, unsigned int N)
{
    int e = start + blockIdx.x * blockDim.x + threadIdx.x;
    if (e < E) {
        unsigned int t = (unsigned int)tgt[e];
        if (t < N) atomicAdd(&out[(size_t)t * D_FEAT], W[e]);
    }
}

// Pass 2: out[n,:] = x[n,:] * s, s = out[n*32].
// 4 float4 elements per thread, batched: issue all 8 loads (4 slot scalars +
// 4 x vectors) before any store -> high MLP, single resident wave.
// stride is a multiple of 8 (float4 units), so each node's 8 slot-readers
// stay within one warp; one __syncwarp() orders all slot reads before the
// slot-overwriting stores.
#define MUL_K 4
__global__ void mul_kernel(const float4* __restrict__ x4,
                           float4* __restrict__ out4,
                           int n_vec, int stride)   // n_vec = N*8
{
    int tid = blockIdx.x * blockDim.x + threadIdx.x;
    const float* out_s = (const float*)out4;

    bool   ok[MUL_K];
    float  s[MUL_K];
    float4 v[MUL_K];

    #pragma unroll
    for (int k = 0; k < MUL_K; k++)
        ok[k] = (tid + k * stride) < n_vec;

    // front-batched loads: 8 outstanding LDGs per thread
    #pragma unroll
    for (int k = 0; k < MUL_K; k++) {
        int idx = tid + k * stride;
        if (ok[k]) {
            s[k] = __ldg(&out_s[(size_t)(idx >> 3) * D_FEAT]);
            v[k] = __ldg(&x4[idx]);
        }
    }

    __syncwarp();

    #pragma unroll
    for (int k = 0; k < MUL_K; k++) {
        int idx = tid + k * stride;
        if (ok[k]) {
            float4 r = v[k];
            float  m = s[k];
            r.x *= m; r.y *= m; r.z *= m; r.w *= m;
            out4[idx] = r;
        }
    }
}

// Inputs (metadata order): edge_index int32 [2, E], x f32 [N, 32], W f32 [E].
// Output: f32 [N, 32].
extern "C" void kernel_launch(void* const* d_in, const int* in_sizes, int n_in,
                              void* d_out, int out_size)
{
    const int*   edge_index = (const int*)d_in[0];
    const float* x          = (const float*)d_in[1];
    const float* W          = (const float*)d_in[2];
    float*       out        = (float*)d_out;

    const int E = in_sizes[2];           // number of edges (= len(W))
    const int N = in_sizes[1] / D_FEAT;  // number of nodes

    const int* tgt = edge_index + (size_t)E;  // second row of [2, E]

    // Pass 0: zero the whole output buffer (contiguous memset node).
    cudaMemsetAsync(out, 0, (size_t)out_size * sizeof(float), 0);

    // Pass 1: segment-sum W by target into out[n*32]
    {
        int n_quads = E / 4;
        int threads = 256;
        int blocks = (n_quads + threads - 1) / threads;
        if (blocks > 0)
            accum_kernel<<<blocks, threads>>>((const int4*)tgt, (const float4*)W,
                                              out, n_quads, (unsigned int)N);
        int tail_start = n_quads * 4;
        if (E - tail_start > 0)
            accum_tail_kernel<<<1, 256>>>(tgt, W, out, tail_start, E,
                                          (unsigned int)N);
    }

    // Pass 2: broadcast multiply (overwrites all of out, including slots)
    {
        int n_vec = N * (D_FEAT / 4);    // N * 8 float4s = 800000
        int threads = 256;
        int total_threads_needed = (n_vec + MUL_K - 1) / MUL_K;
        int blocks = (total_threads_needed + threads - 1) / threads;
        int stride = blocks * threads;   // multiple of 256 -> multiple of 8
        mul_kernel<<<blocks, threads>>>((const float4*)x, (float4*)out,
                                        n_vec, stride);
    }
}

// round 7
// speedup vs baseline: 1.1156x; 1.0884x over previous
#include <cuda_runtime.h>
#include <cuda_bf16.h>
#include <cstdint>

#define D_FEAT 32

// ---------------------------------------------------------------------------
// out[n,:] = x[n,:] * sum_{e: tgt[e]==n} W[e]
// (reference gathers AND scatters on target => the [E,32] message matrix
// factorizes into a scalar segment-sum + broadcast multiply).
//
// Scratch: the reference NEVER reads edge_index[0] (the source row) — only
// edge_index[1]. We repurpose the first N*4 bytes of that dead 6.4MB region
// as the compact per-node accumulator wsum[N]. It is re-zeroed at the start
// of every launch, so every graph replay is deterministic. No allocation,
// d_out is written exactly once per element.
// ---------------------------------------------------------------------------

// Pass 1: scalar segment-sum of W onto wsum. 4 edges per thread (int4+float4
// loads), 4 REDs. RED issue rate is the floor here; loads are fully coalesced.
__global__ void accum_kernel(const int4* __restrict__ tgt4,
                             const float4* __restrict__ W4,
                             float* __restrict__ wsum,
                             int n_quads, unsigned int N)
{
    int i = blockIdx.x * blockDim.x + threadIdx.x;
    if (i < n_quads) {
        int4   t4 = tgt4[i];
        float4 w4 = W4[i];
        unsigned int t;
        t = (unsigned int)t4.x; if (t < N) atomicAdd(&wsum[t], w4.x);
        t = (unsigned int)t4.y; if (t < N) atomicAdd(&wsum[t], w4.y);
        t = (unsigned int)t4.z; if (t < N) atomicAdd(&wsum[t], w4.z);
        t = (unsigned int)t4.w; if (t < N) atomicAdd(&wsum[t], w4.w);
    }
}

// Scalar tail (E % 4 != 0) — not hit for E = 1.6M.
__global__ void accum_tail_kernel(const int* __restrict__ tgt,
                                  const float* __restrict__ W,
                                  float* __restrict__ wsum,
                                  int start, int E, unsigned int N)
{
    int e = start + blockIdx.x * blockDim.x + threadIdx.x;
    if (e < E) {
        unsigned int t = (unsigned int)tgt[e];
        if (t < N) atomicAdd(&wsum[t], W[e]);
    }
}

// Pass 2: out[n,:] = x[n,:] * wsum[n].
// One float4 per (thread, k). A warp's 32 float4s span 4 consecutive nodes,
// so the 32 wsum reads hit ONE 16B span (single L1 wavefront, broadcast).
// No aliasing with out -> no syncwarp, stores retire freely.
#define MUL_K 2
__global__ void mul_kernel(const float4* __restrict__ x4,
                           const float* __restrict__ wsum,
                           float4* __restrict__ out4,
                           int n_vec, int stride)   // n_vec = N*8
{
    int tid = blockIdx.x * blockDim.x + threadIdx.x;

    float  s[MUL_K];
    float4 v[MUL_K];

    // front-batched loads: 4 outstanding LDGs per thread
    #pragma unroll
    for (int k = 0; k < MUL_K; k++) {
        int idx = tid + k * stride;
        if (idx < n_vec) {
            s[k] = __ldg(&wsum[idx >> 3]);
            v[k] = __ldg(&x4[idx]);
        }
    }

    #pragma unroll
    for (int k = 0; k < MUL_K; k++) {
        int idx = tid + k * stride;
        if (idx < n_vec) {
            float4 r = v[k];
            float  m = s[k];
            r.x *= m; r.y *= m; r.z *= m; r.w *= m;
            out4[idx] = r;
        }
    }
}

// Inputs (metadata order): edge_index int32 [2, E], x f32 [N, 32], W f32 [E].
// Output: f32 [N, 32].
extern "C" void kernel_launch(void* const* d_in, const int* in_sizes, int n_in,
                              void* d_out, int out_size)
{
    int*         edge_index = (int*)d_in[0];        // row 0 is dead -> scratch
    const float* x          = (const float*)d_in[1];
    const float* W          = (const float*)d_in[2];
    float*       out        = (float*)d_out;

    const int E = in_sizes[2];           // number of edges (= len(W))
    const int N = in_sizes[1] / D_FEAT;  // number of nodes

    const int* tgt  = edge_index + (size_t)E;  // second row of [2, E] (used)
    float*     wsum = (float*)edge_index;      // first row: never read by ref

    // Pass 0: zero the compact accumulator (400KB, trivial memset node).
    cudaMemsetAsync(wsum, 0, (size_t)N * sizeof(float), 0);

    // Pass 1: segment-sum W by target into wsum
    {
        int n_quads = E / 4;
        int threads = 256;
        int blocks = (n_quads + threads - 1) / threads;
        if (blocks > 0)
            accum_kernel<<<blocks, threads>>>((const int4*)tgt, (const float4*)W,
                                              wsum, n_quads, (unsigned int)N);
        int tail_start = n_quads * 4;
        if (E - tail_start > 0)
            accum_tail_kernel<<<1, 256>>>(tgt, W, wsum, tail_start, E,
                                          (unsigned int)N);
    }

    // Pass 2: broadcast multiply
    {
        int n_vec = N * (D_FEAT / 4);    // N * 8 float4s = 800000
        int threads = 256;
        int total_threads_needed = (n_vec + MUL_K - 1) / MUL_K;
        int blocks = (total_threads_needed + threads - 1) / threads;
        int stride = blocks * threads;   // multiple of 256 -> multiple of 8
        mul_kernel<<<blocks, threads>>>((const float4*)x, wsum, (float4*)out,
                                        n_vec, stride);
    }
}

// round 8
// speedup vs baseline: 1.1330x; 1.0155x over previous
#include <cuda_runtime.h>
#include <cuda_bf16.h>
#include <cstdint>

#define D_FEAT 32

// ---------------------------------------------------------------------------
// out[n,:] = x[n,:] * sum_{e: tgt[e]==n} W[e]
// (reference gathers AND scatters on target => the [E,32] message matrix
// factorizes into a scalar segment-sum + broadcast multiply).
//
// Scratch: reference never reads edge_index[0] (source row); its first N*4
// bytes hold the compact per-node accumulator wsum[N], re-zeroed per launch.
//
// Overlap: accum is LSU-bound (RED issue floor) with DRAM idle; mul is
// DRAM-latency-bound on x. Each accum block issues one TMA-pipe L2 prefetch
// (cp.async.bulk.prefetch.L2.global) covering its slice of x, so x is
// L2-resident by the time mul runs.
// ---------------------------------------------------------------------------

// Pass 1: scalar segment-sum of W onto wsum + L2 prefetch of x.
__global__ void accum_kernel(const int4* __restrict__ tgt4,
                             const float4* __restrict__ W4,
                             float* __restrict__ wsum,
                             const char* __restrict__ x_bytes,
                             unsigned int x_total_bytes,
                             unsigned int chunk_bytes,
                             int n_quads, unsigned int N)
{
    // One TMA-pipe prefetch per block: stream this block's slice of x into L2.
    if (threadIdx.x == 0) {
        unsigned int off = (unsigned int)blockIdx.x * chunk_bytes;
        if (off < x_total_bytes) {
            unsigned int len = x_total_bytes - off;
            if (len > chunk_bytes) len = chunk_bytes;
            len &= ~15u;                      // 16B granularity
            if (len)
                asm volatile("cp.async.bulk.prefetch.L2.global [%0], %1;"
                             :: "l"(x_bytes + off), "r"(len) : "memory");
        }
    }

    int i = blockIdx.x * blockDim.x + threadIdx.x;
    if (i < n_quads) {
        int4   t4 = tgt4[i];
        float4 w4 = W4[i];
        unsigned int t;
        t = (unsigned int)t4.x; if (t < N) atomicAdd(&wsum[t], w4.x);
        t = (unsigned int)t4.y; if (t < N) atomicAdd(&wsum[t], w4.y);
        t = (unsigned int)t4.z; if (t < N) atomicAdd(&wsum[t], w4.z);
        t = (unsigned int)t4.w; if (t < N) atomicAdd(&wsum[t], w4.w);
    }
}

// Scalar tail (E % 4 != 0) — not hit for E = 1.6M.
__global__ void accum_tail_kernel(const int* __restrict__ tgt,
                                  const float* __restrict__ W,
                                  float* __restrict__ wsum,
                                  int start, int E, unsigned int N)
{
    int e = start + blockIdx.x * blockDim.x + threadIdx.x;
    if (e < E) {
        unsigned int t = (unsigned int)tgt[e];
        if (t < N) atomicAdd(&wsum[t], W[e]);
    }
}

// Pass 2: out[n,:] = x[n,:] * wsum[n].
// A warp's 32 float4s span 4 consecutive nodes -> the wsum reads collapse to
// one 16B span. x should now hit L2 thanks to the prefetch.
#define MUL_K 2
__global__ void mul_kernel(const float4* __restrict__ x4,
                           const float* __restrict__ wsum,
                           float4* __restrict__ out4,
                           int n_vec, int stride)   // n_vec = N*8
{
    int tid = blockIdx.x * blockDim.x + threadIdx.x;

    float  s[MUL_K];
    float4 v[MUL_K];

    #pragma unroll
    for (int k = 0; k < MUL_K; k++) {
        int idx = tid + k * stride;
        if (idx < n_vec) {
            s[k] = __ldg(&wsum[idx >> 3]);
            v[k] = __ldg(&x4[idx]);
        }
    }

    #pragma unroll
    for (int k = 0; k < MUL_K; k++) {
        int idx = tid + k * stride;
        if (idx < n_vec) {
            float4 r = v[k];
            float  m = s[k];
            r.x *= m; r.y *= m; r.z *= m; r.w *= m;
            out4[idx] = r;
        }
    }
}

// Inputs (metadata order): edge_index int32 [2, E], x f32 [N, 32], W f32 [E].
// Output: f32 [N, 32].
extern "C" void kernel_launch(void* const* d_in, const int* in_sizes, int n_in,
                              void* d_out, int out_size)
{
    int*         edge_index = (int*)d_in[0];        // row 0 is dead -> scratch
    const float* x          = (const float*)d_in[1];
    const float* W          = (const float*)d_in[2];
    float*       out        = (float*)d_out;

    const int E = in_sizes[2];           // number of edges (= len(W))
    const int N = in_sizes[1] / D_FEAT;  // number of nodes

    const int* tgt  = edge_index + (size_t)E;  // second row of [2, E] (used)
    float*     wsum = (float*)edge_index;      // first row: never read by ref

    // Pass 0: zero the compact accumulator (400KB memset node).
    cudaMemsetAsync(wsum, 0, (size_t)N * sizeof(float), 0);

    // Pass 1: segment-sum W by target into wsum (+ x prefetch to L2)
    {
        int n_quads = E / 4;
        int threads = 256;
        int blocks = (n_quads + threads - 1) / threads;
        unsigned int x_total_bytes = (unsigned int)in_sizes[1] * 4u;
        unsigned int chunk = (x_total_bytes + blocks - 1) / blocks;
        chunk = (chunk + 15u) & ~15u;            // round up to 16B
        if (blocks > 0)
            accum_kernel<<<blocks, threads>>>((const int4*)tgt, (const float4*)W,
                                              wsum, (const char*)x,
                                              x_total_bytes, chunk,
                                              n_quads, (unsigned int)N);
        int tail_start = n_quads * 4;
        if (E - tail_start > 0)
            accum_tail_kernel<<<1, 256>>>(tgt, W, wsum, tail_start, E,
                                          (unsigned int)N);
    }

    // Pass 2: broadcast multiply
    {
        int n_vec = N * (D_FEAT / 4);    // N * 8 float4s = 800000
        int threads = 256;
        int total_threads_needed = (n_vec + MUL_K - 1) / MUL_K;
        int blocks = (total_threads_needed + threads - 1) / threads;
        int stride = blocks * threads;   // multiple of 256 -> multiple of 8
        mul_kernel<<<blocks, threads>>>((const float4*)x, wsum, (float4*)out,
                                        n_vec, stride);
    }
}